// round 14
// baseline (speedup 1.0000x reference)
#include <cuda_runtime.h>

#define BB 32
#define NP1 2048
#define NP2 1024
#define NP3 512
#define KK1 6
#define KK2 4
#define KK3 3

// scratch (static device globals; no allocation)
__device__ float g_uv[BB * NP1 * 128];
__device__ float g_h1[BB * NP1 * 64];
__device__ int   g_idx1[BB * NP1 * KK1];
__device__ int   g_sel1[BB * NP2];
__device__ float g_pos2[BB * NP2 * 3];
__device__ int   g_idx2[BB * NP2 * KK2];
__device__ float g_h2[BB * NP2 * 64];
__device__ int   g_sel2[BB * NP3];
__device__ float g_pos3[BB * NP3 * 3];
__device__ int   g_idx3[BB * NP3 * KK3];
__device__ float g_h3[BB * NP3 * 64];

// ================= device bodies =================

// kNN body: whole graph in smem, per-thread K-insertion (stable ties = top_k)
template<int NP, int K>
__device__ __forceinline__ void knn_body(const float* __restrict__ pos,
                                         int* __restrict__ idx,
                                         int blk, float4* sp) {
    const int t = threadIdx.x;
    const int bpg = NP / 256;
    const int b = blk / bpg;
    const int q0 = (blk % bpg) * 256;
    const float* p = pos + b * NP * 3;
    for (int i = t; i < NP; i += 256)
        sp[i] = make_float4(p[3*i], p[3*i+1], p[3*i+2], 0.f);
    __syncthreads();
    const int q = q0 + t;
    const float4 pq = sp[q];
    float bd[K]; int bi[K];
#pragma unroll
    for (int u = 0; u < K; u++) { bd[u] = 3.4e38f; bi[u] = 0; }
#pragma unroll 4
    for (int j = 0; j < NP; j++) {
        float4 pj = sp[j];
        float dx = pq.x - pj.x, dy = pq.y - pj.y, dz = pq.z - pj.z;
        float dd = fmaf(dx, dx, fmaf(dy, dy, dz * dz));
        if (dd < bd[K-1]) {
            bd[K-1] = dd; bi[K-1] = j;
#pragma unroll
            for (int u = K-1; u > 0; u--) {
                if (bd[u] < bd[u-1]) {
                    float tf = bd[u]; bd[u] = bd[u-1]; bd[u-1] = tf;
                    int   ti = bi[u]; bi[u] = bi[u-1]; bi[u-1] = ti;
                }
            }
        }
    }
#pragma unroll
    for (int u = 0; u < K; u++) idx[(b*NP + q)*K + u] = bi[u];
}

// FPS body (R8/R11-validated) + direct sampled-pos writeout
template<int NP, int M>
__device__ __forceinline__ void fps_body(const float* __restrict__ pos,
                                         int* __restrict__ sel,
                                         float* __restrict__ posout,
                                         int b, float4* sp) {
    const int t = threadIdx.x;
    constexpr int T = 256;
    constexpr int E = NP / T;
    __shared__ float swv[2][8];
    __shared__ int   swi[2][8];
    const float* p = pos + b * NP * 3;
    for (int i = t; i < NP; i += T)
        sp[i] = make_float4(p[3*i], p[3*i+1], p[3*i+2], 0.f);
    __syncthreads();
    float d[E], px[E], py[E], pz[E];
#pragma unroll
    for (int s = 0; s < E; s++) {
        float4 q = sp[t*E + s];
        px[s] = q.x; py[s] = q.y; pz[s] = q.z;
        d[s] = 3.4e38f;
    }
    if (t == 0) {
        sel[b*M] = 0;
        posout[b*M*3]     = sp[0].x;
        posout[b*M*3 + 1] = sp[0].y;
        posout[b*M*3 + 2] = sp[0].z;
    }
    float cx = sp[0].x, cy = sp[0].y, cz = sp[0].z;
    const int warp = t >> 5, lane = t & 31;
    for (int it = 1; it < M; it++) {
        float bv = 0.f; int bidx = t*E;
#pragma unroll
        for (int s = 0; s < E; s++) {
            float dx = px[s]-cx, dy = py[s]-cy, dz = pz[s]-cz;
            float nd = fmaf(dx, dx, fmaf(dy, dy, dz*dz));
            float dn = fminf(d[s], nd);
            d[s] = dn;
            if (dn > bv) { bv = dn; bidx = t*E + s; }
        }
        unsigned mu = __reduce_max_sync(0xffffffffu, __float_as_uint(bv));
        unsigned mk = __ballot_sync(0xffffffffu, __float_as_uint(bv) == mu);
        int src = __ffs(mk) - 1;
        int widx = __shfl_sync(0xffffffffu, bidx, src);
        const int par = it & 1;
        if (lane == 0) { swv[par][warp] = __uint_as_float(mu); swi[par][warp] = widx; }
        __syncthreads();
        float fv = swv[par][0]; int fi = swi[par][0];
#pragma unroll
        for (int w = 1; w < 8; w++) {
            float wv = swv[par][w];
            if (wv > fv) { fv = wv; fi = swi[par][w]; }
        }
        float4 c = sp[fi];
        if (t == 0) {
            sel[b*M + it] = fi;
            posout[(b*M + it)*3]     = c.x;
            posout[(b*M + it)*3 + 1] = c.y;
            posout[(b*M + it)*3 + 2] = c.z;
        }
        cx = c.x; cy = c.y; cz = c.z;
    }
}

// edge MLP body v2 (R11/R12-validated): register K-max, direct store
template<int NP, int K, int PT>
__device__ __forceinline__ void edge_body(
    const float* __restrict__ pos, const int* __restrict__ idx,
    const float* __restrict__ UV, const float* __restrict__ Wrel,
    const float* __restrict__ ba, const float* __restrict__ Wb,
    const float* __restrict__ bb, float* __restrict__ hout,
    int blk, float* smdyn)
{
    constexpr int E   = PT * K;
    constexpr int KP  = (K == 3) ? 4 : K;
    constexpr int EPP = PT * KP + 8;
    constexpr int CW  = PT / 4;
    constexpr int NCG = 64 / CW;
    float* sHid = smdyn;               // [64][EPP]
    float* sWb  = smdyn + 64 * EPP;    // [64][64]
    __shared__ float sWrel[192], sba[64], sbb[64];
    __shared__ int   sJ[E];
    __shared__ float sRx[E], sRy[E], sRz[E];

    const int t  = threadIdx.x;
    const int p0 = blk * PT;
    const int b  = p0 / NP;
    const int i0 = p0 - b * NP;

    for (int x = t; x < 4096; x += 256) sWb[x] = Wb[x];
    if (t < 192) sWrel[t] = Wrel[t];
    if (t < 64) { sba[t] = ba[t]; sbb[t] = bb[t]; }
    for (int e = t; e < E; e += 256) {
        int pl = e / K, kk = e - pl*K;
        int il = i0 + pl;
        int j  = idx[(b*NP + il)*K + kk];
        sJ[e] = j;
        int ig = (b*NP + il)*3, jg = (b*NP + j)*3;
        sRx[e] = pos[jg]   - pos[ig];
        sRy[e] = pos[jg+1] - pos[ig+1];
        sRz[e] = pos[jg+2] - pos[ig+2];
    }
    __syncthreads();

    for (int x = t; x < E*64; x += 256) {
        int c = x & 63, e = x >> 6;
        int pl = e / K, kk = e - pl*K;
        int ig = b*NP + i0 + pl;
        int jg = b*NP + sJ[e];
        float v = UV[ig*128 + c] + UV[jg*128 + 64 + c] + sba[c];
        v = fmaf(sRx[e], sWrel[c],       v);
        v = fmaf(sRy[e], sWrel[64 + c],  v);
        v = fmaf(sRz[e], sWrel[128 + c], v);
        sHid[c*EPP + pl*KP + kk] = fmaxf(v, 0.f);
    }
    __syncthreads();

    const int pl = t / NCG;
    const int c0 = (t % NCG) * CW;
    float acc[K][CW];
#pragma unroll
    for (int kk = 0; kk < K; kk++)
#pragma unroll
        for (int c = 0; c < CW; c++) acc[kk][c] = 0.f;
#pragma unroll 2
    for (int k = 0; k < 64; k++) {
        const float* hb = &sHid[k*EPP + pl*KP];
        float hv[K];
        if constexpr (KP == 4) {
            float4 h4 = *(const float4*)hb;
            hv[0] = h4.x; hv[1] = h4.y; hv[2] = h4.z;
            if constexpr (K == 4) hv[3] = h4.w;
        } else {   // K = 6
            float2 a = *(const float2*)hb;
            float2 bq = *(const float2*)(hb + 2);
            float2 cq = *(const float2*)(hb + 4);
            hv[0] = a.x; hv[1] = a.y; hv[2] = bq.x;
            hv[3] = bq.y; hv[4] = cq.x; hv[5] = cq.y;
        }
        float wv[CW];
#pragma unroll
        for (int g = 0; g < CW/4; g++) {
            float4 w = *(const float4*)&sWb[k*64 + c0 + g*4];
            wv[g*4] = w.x; wv[g*4+1] = w.y; wv[g*4+2] = w.z; wv[g*4+3] = w.w;
        }
#pragma unroll
        for (int kk = 0; kk < K; kk++)
#pragma unroll
            for (int c = 0; c < CW; c++)
                acc[kk][c] = fmaf(hv[kk], wv[c], acc[kk][c]);
    }
    float* orow = hout + (p0 + pl)*64 + c0;
#pragma unroll
    for (int g = 0; g < CW/4; g++) {
        float o[4];
#pragma unroll
        for (int q = 0; q < 4; q++) {
            int c = g*4 + q;
            float m = acc[0][c];
#pragma unroll
            for (int kk = 1; kk < K; kk++) m = fmaxf(m, acc[kk][c]);
            o[q] = fmaxf(m + sbb[c0 + c], 0.f);
        }
        *(float4*)&orow[g*4] = make_float4(o[0], o[1], o[2], o[3]);
    }
}

// uv CI=3 body (layer 1): 32 rows/block
__device__ __forceinline__ void uv3_body(const float* __restrict__ H,
                                         const float* __restrict__ Wa,
                                         float* __restrict__ UV,
                                         int blk, float* sB) {
    const int tid = threadIdx.x;
    for (int x = tid; x < 384; x += 256) {
        int dd = x >> 7, c = x & 127;
        sB[x] = (c < 64) ? Wa[dd*64 + c] : Wa[(3 + dd)*64 + (c - 64)];
    }
    __syncthreads();
    const int warp = tid >> 5, lane = tid & 31;
    const int c0 = lane * 4;
    for (int rr = 0; rr < 4; rr++) {
        int row = blk * 32 + warp * 4 + rr;
        float hx = H[row*3], hy = H[row*3+1], hz = H[row*3+2];
        float4 b0 = *reinterpret_cast<const float4*>(&sB[c0]);
        float4 b1 = *reinterpret_cast<const float4*>(&sB[128 + c0]);
        float4 b2 = *reinterpret_cast<const float4*>(&sB[256 + c0]);
        float a0 = hx*b0.x + hy*b1.x + hz*b2.x;
        float a1 = hx*b0.y + hy*b1.y + hz*b2.y;
        float a2 = hx*b0.z + hy*b1.z + hz*b2.z;
        float a3 = hx*b0.w + hy*b1.w + hz*b2.w;
        *reinterpret_cast<float4*>(&UV[row*128 + c0]) = make_float4(a0, a1, a2, a3);
    }
}

// uv CI=64 body with fused sel-gather: UV[row] = H[sel[row]] @ [Wtop|Wmid]
template<int NPIN, int MS>
__device__ __forceinline__ void uv64g_body(const float* __restrict__ H,
                                           const int* __restrict__ sel,
                                           const float* __restrict__ Wa,
                                           float* __restrict__ UV,
                                           int blk, float* sm) {
    float* sH = sm;            // [64][68] transposed
    float* sB = sm + 64*68;    // [64][128]
    const int tid = threadIdx.x;
    const int row0 = blk * 64;
    const int b = row0 / MS;
    for (int x = tid; x < 8192; x += 256) {
        int dd = x >> 7, c = x & 127;
        sB[x] = (c < 64) ? Wa[dd*64 + c] : Wa[(64 + dd)*64 + (c - 64)];
    }
    for (int i = tid; i < 4096; i += 256) {
        int r = i >> 6, k = i & 63;
        int srow = sel[row0 + r];
        sH[k*68 + r] = H[(b*NPIN + srow)*64 + k];
    }
    __syncthreads();
    const int r0 = (tid >> 4) * 4;
    const int c0 = (tid & 15) * 8;
    float acc[4][8];
#pragma unroll
    for (int r = 0; r < 4; r++)
#pragma unroll
        for (int c = 0; c < 8; c++) acc[r][c] = 0.f;
#pragma unroll 4
    for (int k = 0; k < 64; k++) {
        float4 h  = *(const float4*)&sH[k*68 + r0];
        float4 w0 = *(const float4*)&sB[k*128 + c0];
        float4 w1 = *(const float4*)&sB[k*128 + c0 + 4];
        float hv[4] = {h.x, h.y, h.z, h.w};
        float wv[8] = {w0.x, w0.y, w0.z, w0.w, w1.x, w1.y, w1.z, w1.w};
#pragma unroll
        for (int r = 0; r < 4; r++)
#pragma unroll
            for (int c = 0; c < 8; c++)
                acc[r][c] = fmaf(hv[r], wv[c], acc[r][c]);
    }
#pragma unroll
    for (int r = 0; r < 4; r++) {
        *(float4*)&UV[(row0 + r0 + r)*128 + c0]     = make_float4(acc[r][0], acc[r][1], acc[r][2], acc[r][3]);
        *(float4*)&UV[(row0 + r0 + r)*128 + c0 + 4] = make_float4(acc[r][4], acc[r][5], acc[r][6], acc[r][7]);
    }
}

// ================= kernels =================

// pre: knn1 || uv1  (both read only pos)
__global__ void __launch_bounds__(256) pre1_kernel(const float* __restrict__ pos,
                                                   int* __restrict__ idx1,
                                                   const float* __restrict__ W1a,
                                                   float* __restrict__ UV) {
    extern __shared__ float smd[];
    if (blockIdx.x < BB*NP1/256)
        knn_body<NP1, KK1>(pos, idx1, blockIdx.x, (float4*)smd);
    else
        uv3_body(pos, W1a, UV, blockIdx.x - BB*NP1/256, smd);
}

// A: fps1 (writes sel1+pos2) || edge1
__global__ void __launch_bounds__(256) fpsedge1_kernel(
    const float* __restrict__ pos, int* __restrict__ sel1, float* __restrict__ pos2,
    const int* __restrict__ idx1, const float* __restrict__ UV,
    const float* __restrict__ Wrel, const float* __restrict__ ba,
    const float* __restrict__ Wb, const float* __restrict__ bb,
    float* __restrict__ h1)
{
    extern __shared__ float smd[];
    if (blockIdx.x < BB)
        fps_body<NP1, NP2>(pos, sel1, pos2, blockIdx.x, (float4*)smd);
    else
        edge_body<NP1, KK1, 32>(pos, idx1, UV, Wrel, ba, Wb, bb, h1, blockIdx.x - BB, smd);
}

// B: fps2 (writes sel2+pos3) || knn2 || uv2-gather
__global__ void __launch_bounds__(256) mid2_kernel(
    const float* __restrict__ pos2, int* __restrict__ sel2, float* __restrict__ pos3,
    int* __restrict__ idx2, const float* __restrict__ h1, const int* __restrict__ sel1,
    const float* __restrict__ W2a, float* __restrict__ UV)
{
    extern __shared__ float smd[];
    if (blockIdx.x < BB)
        fps_body<NP2, NP3>(pos2, sel2, pos3, blockIdx.x, (float4*)smd);
    else if (blockIdx.x < BB + BB*NP2/256)
        knn_body<NP2, KK2>(pos2, idx2, blockIdx.x - BB, (float4*)smd);
    else
        uv64g_body<NP1, NP2>(h1, sel1, W2a, UV, blockIdx.x - BB - BB*NP2/256, smd);
}

// C: edge2 || knn3
__global__ void __launch_bounds__(256) c3_kernel(
    const float* __restrict__ pos2, const int* __restrict__ idx2,
    const float* __restrict__ UV, const float* __restrict__ Wrel,
    const float* __restrict__ ba, const float* __restrict__ Wb,
    const float* __restrict__ bb, float* __restrict__ h2,
    const float* __restrict__ pos3, int* __restrict__ idx3)
{
    extern __shared__ float smd[];
    if (blockIdx.x < BB*NP2/32)
        edge_body<NP2, KK2, 32>(pos2, idx2, UV, Wrel, ba, Wb, bb, h2, blockIdx.x, smd);
    else
        knn_body<NP3, KK3>(pos3, idx3, blockIdx.x - BB*NP2/32, (float4*)smd);
}

// D: uv3-gather
__global__ void __launch_bounds__(256) uv3g_kernel(
    const float* __restrict__ h2, const int* __restrict__ sel2,
    const float* __restrict__ W3a, float* __restrict__ UV)
{
    extern __shared__ float smd[];
    uv64g_body<NP2, NP3>(h2, sel2, W3a, UV, blockIdx.x, smd);
}

// E: edge3
__global__ void __launch_bounds__(256) edge3_kernel(
    const float* __restrict__ pos3, const int* __restrict__ idx3,
    const float* __restrict__ UV, const float* __restrict__ Wrel,
    const float* __restrict__ ba, const float* __restrict__ Wb,
    const float* __restrict__ bb, float* __restrict__ h3)
{
    extern __shared__ float smd[];
    edge_body<NP3, KK3, 64>(pos3, idx3, UV, Wrel, ba, Wb, bb, h3, blockIdx.x, smd);
}

// head: global max-pool + [64x6] linear
__global__ void __launch_bounds__(64) head_kernel(const float* __restrict__ h3,
                                                  const float* __restrict__ Wr,
                                                  const float* __restrict__ br,
                                                  float* __restrict__ out) {
    __shared__ float g[64];
    const int b = blockIdx.x, c = threadIdx.x;
    float m = -3.4e38f;
#pragma unroll 2
    for (int p = 0; p < NP3; p++) m = fmaxf(m, h3[(b*NP3 + p)*64 + c]);
    g[c] = m;
    __syncthreads();
    if (c < 6) {
        float s = br[c];
#pragma unroll
        for (int dd = 0; dd < 64; dd++) s = fmaf(g[dd], Wr[dd*6 + c], s);
        out[b*6 + c] = s;
    }
}

extern "C" void kernel_launch(void* const* d_in, const int* in_sizes, int n_in,
                              void* d_out, int out_size) {
    const float* pos = (const float*)d_in[1];
    const float* W1a = (const float*)d_in[3];  const float* b1a = (const float*)d_in[4];
    const float* W1b = (const float*)d_in[5];  const float* b1b = (const float*)d_in[6];
    const float* W2a = (const float*)d_in[7];  const float* b2a = (const float*)d_in[8];
    const float* W2b = (const float*)d_in[9];  const float* b2b = (const float*)d_in[10];
    const float* W3a = (const float*)d_in[11]; const float* b3a = (const float*)d_in[12];
    const float* W3b = (const float*)d_in[13]; const float* b3b = (const float*)d_in[14];
    const float* Wr  = (const float*)d_in[15]; const float* br  = (const float*)d_in[16];
    float* out = (float*)d_out;

    const int smemPre = NP1 * 16;                         // 32768
    const int smemA   = (64*(32*KK1 + 8) + 4096) * 4;     // 67584 (R12-proven: 3 blk/SM)
    const int smemB   = (64*68 + 64*128) * 4;             // 50176
    const int smemC   = (64*(32*KK2 + 8) + 4096) * 4;     // 51200
    const int smemE   = (64*(64*4  + 8) + 4096) * 4;      // 83968
    cudaFuncSetAttribute(fpsedge1_kernel, cudaFuncAttributeMaxDynamicSharedMemorySize, smemA);
    cudaFuncSetAttribute(mid2_kernel,     cudaFuncAttributeMaxDynamicSharedMemorySize, smemB);
    cudaFuncSetAttribute(c3_kernel,       cudaFuncAttributeMaxDynamicSharedMemorySize, smemC);
    cudaFuncSetAttribute(uv3g_kernel,     cudaFuncAttributeMaxDynamicSharedMemorySize, smemB);
    cudaFuncSetAttribute(edge3_kernel,    cudaFuncAttributeMaxDynamicSharedMemorySize, smemE);

    float *uv, *h1, *pos2, *h2, *pos3, *h3;
    int *idx1, *sel1, *idx2, *sel2, *idx3;
    cudaGetSymbolAddress((void**)&uv,   g_uv);
    cudaGetSymbolAddress((void**)&h1,   g_h1);
    cudaGetSymbolAddress((void**)&idx1, g_idx1);
    cudaGetSymbolAddress((void**)&sel1, g_sel1);
    cudaGetSymbolAddress((void**)&pos2, g_pos2);
    cudaGetSymbolAddress((void**)&idx2, g_idx2);
    cudaGetSymbolAddress((void**)&h2,   g_h2);
    cudaGetSymbolAddress((void**)&sel2, g_sel2);
    cudaGetSymbolAddress((void**)&pos3, g_pos3);
    cudaGetSymbolAddress((void**)&idx3, g_idx3);
    cudaGetSymbolAddress((void**)&h3,   g_h3);

    // pre: knn1 || uv1
    pre1_kernel<<<BB*NP1/256 + BB*NP1/32, 256, smemPre>>>(pos, idx1, W1a, uv);
    // A: fps1 || edge1
    fpsedge1_kernel<<<BB + BB*NP1/32, 256, smemA>>>(
        pos, sel1, pos2, idx1, uv, W1a + 6*64, b1a, W1b, b1b, h1);
    // B: fps2 || knn2 || uv2-gather
    mid2_kernel<<<BB + BB*NP2/256 + BB*NP2/64, 256, smemB>>>(
        pos2, sel2, pos3, idx2, h1, sel1, W2a, uv);
    // C: edge2 || knn3
    c3_kernel<<<BB*NP2/32 + BB*NP3/256, 256, smemC>>>(
        pos2, idx2, uv, W2a + 128*64, b2a, W2b, b2b, h2, pos3, idx3);
    // D: uv3-gather
    uv3g_kernel<<<BB*NP3/64, 256, smemB>>>(h2, sel2, W3a, uv);
    // E: edge3
    edge3_kernel<<<BB*NP3/64, 256, smemE>>>(pos3, idx3, uv, W3a + 128*64, b3a, W3b, b3b, h3);
    // head
    head_kernel<<<BB, 64>>>(h3, Wr, br, out);
}

// round 17
// speedup vs baseline: 1.1081x; 1.1081x over previous
#include <cuda_runtime.h>

#define BB 32
#define NP1 2048
#define NP2 1024
#define NP3 512
#define KK1 6
#define KK2 4
#define KK3 3

// scratch (static device globals; no allocation)
__device__ float g_uv[BB * NP1 * 128];
__device__ float g_h1[BB * NP1 * 64];
__device__ int   g_idx1[BB * NP1 * KK1];
__device__ int   g_sel1[BB * NP2];
__device__ float g_pos2[BB * NP2 * 3];
__device__ int   g_idx2[BB * NP2 * KK2];
__device__ float g_h2[BB * NP2 * 64];
__device__ int   g_sel2[BB * NP3];
__device__ float g_pos3[BB * NP3 * 3];
__device__ int   g_idx3[BB * NP3 * KK3];
__device__ float g_h3[BB * NP3 * 64];

// ================= device bodies (all R14-validated) =================

template<int NP, int K>
__device__ __forceinline__ void knn_body(const float* __restrict__ pos,
                                         int* __restrict__ idx,
                                         int blk, float4* sp) {
    const int t = threadIdx.x;
    const int bpg = NP / 256;
    const int b = blk / bpg;
    const int q0 = (blk % bpg) * 256;
    const float* p = pos + b * NP * 3;
    for (int i = t; i < NP; i += 256)
        sp[i] = make_float4(p[3*i], p[3*i+1], p[3*i+2], 0.f);
    __syncthreads();
    const int q = q0 + t;
    const float4 pq = sp[q];
    float bd[K]; int bi[K];
#pragma unroll
    for (int u = 0; u < K; u++) { bd[u] = 3.4e38f; bi[u] = 0; }
#pragma unroll 4
    for (int j = 0; j < NP; j++) {
        float4 pj = sp[j];
        float dx = pq.x - pj.x, dy = pq.y - pj.y, dz = pq.z - pj.z;
        float dd = fmaf(dx, dx, fmaf(dy, dy, dz * dz));
        if (dd < bd[K-1]) {
            bd[K-1] = dd; bi[K-1] = j;
#pragma unroll
            for (int u = K-1; u > 0; u--) {
                if (bd[u] < bd[u-1]) {
                    float tf = bd[u]; bd[u] = bd[u-1]; bd[u-1] = tf;
                    int   ti = bi[u]; bi[u] = bi[u-1]; bi[u-1] = ti;
                }
            }
        }
    }
#pragma unroll
    for (int u = 0; u < K; u++) idx[(b*NP + q)*K + u] = bi[u];
}

template<int NP, int M>
__device__ __forceinline__ void fps_body(const float* __restrict__ pos,
                                         int* __restrict__ sel,
                                         float* __restrict__ posout,
                                         int b, float4* sp) {
    const int t = threadIdx.x;
    constexpr int T = 256;
    constexpr int E = NP / T;
    __shared__ float swv[2][8];
    __shared__ int   swi[2][8];
    const float* p = pos + b * NP * 3;
    for (int i = t; i < NP; i += T)
        sp[i] = make_float4(p[3*i], p[3*i+1], p[3*i+2], 0.f);
    __syncthreads();
    float d[E], px[E], py[E], pz[E];
#pragma unroll
    for (int s = 0; s < E; s++) {
        float4 q = sp[t*E + s];
        px[s] = q.x; py[s] = q.y; pz[s] = q.z;
        d[s] = 3.4e38f;
    }
    if (t == 0) {
        sel[b*M] = 0;
        posout[b*M*3]     = sp[0].x;
        posout[b*M*3 + 1] = sp[0].y;
        posout[b*M*3 + 2] = sp[0].z;
    }
    float cx = sp[0].x, cy = sp[0].y, cz = sp[0].z;
    const int warp = t >> 5, lane = t & 31;
    for (int it = 1; it < M; it++) {
        float bv = 0.f; int bidx = t*E;
#pragma unroll
        for (int s = 0; s < E; s++) {
            float dx = px[s]-cx, dy = py[s]-cy, dz = pz[s]-cz;
            float nd = fmaf(dx, dx, fmaf(dy, dy, dz*dz));
            float dn = fminf(d[s], nd);
            d[s] = dn;
            if (dn > bv) { bv = dn; bidx = t*E + s; }
        }
        unsigned mu = __reduce_max_sync(0xffffffffu, __float_as_uint(bv));
        unsigned mk = __ballot_sync(0xffffffffu, __float_as_uint(bv) == mu);
        int src = __ffs(mk) - 1;
        int widx = __shfl_sync(0xffffffffu, bidx, src);
        const int par = it & 1;
        if (lane == 0) { swv[par][warp] = __uint_as_float(mu); swi[par][warp] = widx; }
        __syncthreads();
        float fv = swv[par][0]; int fi = swi[par][0];
#pragma unroll
        for (int w = 1; w < 8; w++) {
            float wv = swv[par][w];
            if (wv > fv) { fv = wv; fi = swi[par][w]; }
        }
        float4 c = sp[fi];
        if (t == 0) {
            sel[b*M + it] = fi;
            posout[(b*M + it)*3]     = c.x;
            posout[(b*M + it)*3 + 1] = c.y;
            posout[(b*M + it)*3 + 2] = c.z;
        }
        cx = c.x; cy = c.y; cz = c.z;
    }
}

template<int NP, int K, int PT>
__device__ __forceinline__ void edge_body(
    const float* __restrict__ pos, const int* __restrict__ idx,
    const float* __restrict__ UV, const float* __restrict__ Wrel,
    const float* __restrict__ ba, const float* __restrict__ Wb,
    const float* __restrict__ bb, float* __restrict__ hout,
    int blk, float* smdyn)
{
    constexpr int E   = PT * K;
    constexpr int KP  = (K == 3) ? 4 : K;
    constexpr int EPP = PT * KP + 8;
    constexpr int CW  = PT / 4;
    constexpr int NCG = 64 / CW;
    float* sHid = smdyn;               // [64][EPP]
    float* sWb  = smdyn + 64 * EPP;    // [64][64]
    __shared__ float sWrel[192], sba[64], sbb[64];
    __shared__ int   sJ[E];
    __shared__ float sRx[E], sRy[E], sRz[E];

    const int t  = threadIdx.x;
    const int p0 = blk * PT;
    const int b  = p0 / NP;
    const int i0 = p0 - b * NP;

    for (int x = t; x < 4096; x += 256) sWb[x] = Wb[x];
    if (t < 192) sWrel[t] = Wrel[t];
    if (t < 64) { sba[t] = ba[t]; sbb[t] = bb[t]; }
    for (int e = t; e < E; e += 256) {
        int pl = e / K, kk = e - pl*K;
        int il = i0 + pl;
        int j  = idx[(b*NP + il)*K + kk];
        sJ[e] = j;
        int ig = (b*NP + il)*3, jg = (b*NP + j)*3;
        sRx[e] = pos[jg]   - pos[ig];
        sRy[e] = pos[jg+1] - pos[ig+1];
        sRz[e] = pos[jg+2] - pos[ig+2];
    }
    __syncthreads();

    for (int x = t; x < E*64; x += 256) {
        int c = x & 63, e = x >> 6;
        int pl = e / K, kk = e - pl*K;
        int ig = b*NP + i0 + pl;
        int jg = b*NP + sJ[e];
        float v = UV[ig*128 + c] + UV[jg*128 + 64 + c] + sba[c];
        v = fmaf(sRx[e], sWrel[c],       v);
        v = fmaf(sRy[e], sWrel[64 + c],  v);
        v = fmaf(sRz[e], sWrel[128 + c], v);
        sHid[c*EPP + pl*KP + kk] = fmaxf(v, 0.f);
    }
    __syncthreads();

    const int pl = t / NCG;
    const int c0 = (t % NCG) * CW;
    float acc[K][CW];
#pragma unroll
    for (int kk = 0; kk < K; kk++)
#pragma unroll
        for (int c = 0; c < CW; c++) acc[kk][c] = 0.f;
#pragma unroll 2
    for (int k = 0; k < 64; k++) {
        const float* hb = &sHid[k*EPP + pl*KP];
        float hv[K];
        if constexpr (KP == 4) {
            float4 h4 = *(const float4*)hb;
            hv[0] = h4.x; hv[1] = h4.y; hv[2] = h4.z;
            if constexpr (K == 4) hv[3] = h4.w;
        } else {   // K = 6
            float2 a = *(const float2*)hb;
            float2 bq = *(const float2*)(hb + 2);
            float2 cq = *(const float2*)(hb + 4);
            hv[0] = a.x; hv[1] = a.y; hv[2] = bq.x;
            hv[3] = bq.y; hv[4] = cq.x; hv[5] = cq.y;
        }
        float wv[CW];
#pragma unroll
        for (int g = 0; g < CW/4; g++) {
            float4 w = *(const float4*)&sWb[k*64 + c0 + g*4];
            wv[g*4] = w.x; wv[g*4+1] = w.y; wv[g*4+2] = w.z; wv[g*4+3] = w.w;
        }
#pragma unroll
        for (int kk = 0; kk < K; kk++)
#pragma unroll
            for (int c = 0; c < CW; c++)
                acc[kk][c] = fmaf(hv[kk], wv[c], acc[kk][c]);
    }
    float* orow = hout + (p0 + pl)*64 + c0;
#pragma unroll
    for (int g = 0; g < CW/4; g++) {
        float o[4];
#pragma unroll
        for (int q = 0; q < 4; q++) {
            int c = g*4 + q;
            float m = acc[0][c];
#pragma unroll
            for (int kk = 1; kk < K; kk++) m = fmaxf(m, acc[kk][c]);
            o[q] = fmaxf(m + sbb[c0 + c], 0.f);
        }
        *(float4*)&orow[g*4] = make_float4(o[0], o[1], o[2], o[3]);
    }
}

__device__ __forceinline__ void uv3_body(const float* __restrict__ H,
                                         const float* __restrict__ Wa,
                                         float* __restrict__ UV,
                                         int blk, float* sB) {
    const int tid = threadIdx.x;
    for (int x = tid; x < 384; x += 256) {
        int dd = x >> 7, c = x & 127;
        sB[x] = (c < 64) ? Wa[dd*64 + c] : Wa[(3 + dd)*64 + (c - 64)];
    }
    __syncthreads();
    const int warp = tid >> 5, lane = tid & 31;
    const int c0 = lane * 4;
    for (int rr = 0; rr < 4; rr++) {
        int row = blk * 32 + warp * 4 + rr;
        float hx = H[row*3], hy = H[row*3+1], hz = H[row*3+2];
        float4 b0 = *reinterpret_cast<const float4*>(&sB[c0]);
        float4 b1 = *reinterpret_cast<const float4*>(&sB[128 + c0]);
        float4 b2 = *reinterpret_cast<const float4*>(&sB[256 + c0]);
        float a0 = hx*b0.x + hy*b1.x + hz*b2.x;
        float a1 = hx*b0.y + hy*b1.y + hz*b2.y;
        float a2 = hx*b0.z + hy*b1.z + hz*b2.z;
        float a3 = hx*b0.w + hy*b1.w + hz*b2.w;
        *reinterpret_cast<float4*>(&UV[row*128 + c0]) = make_float4(a0, a1, a2, a3);
    }
}

template<int NPIN, int MS>
__device__ __forceinline__ void uv64g_body(const float* __restrict__ H,
                                           const int* __restrict__ sel,
                                           const float* __restrict__ Wa,
                                           float* __restrict__ UV,
                                           int blk, float* sm) {
    float* sH = sm;            // [64][68] transposed
    float* sB = sm + 64*68;    // [64][128]
    const int tid = threadIdx.x;
    const int row0 = blk * 64;
    const int b = row0 / MS;
    for (int x = tid; x < 8192; x += 256) {
        int dd = x >> 7, c = x & 127;
        sB[x] = (c < 64) ? Wa[dd*64 + c] : Wa[(64 + dd)*64 + (c - 64)];
    }
    for (int i = tid; i < 4096; i += 256) {
        int r = i >> 6, k = i & 63;
        int srow = sel[row0 + r];
        sH[k*68 + r] = H[(b*NPIN + srow)*64 + k];
    }
    __syncthreads();
    const int r0 = (tid >> 4) * 4;
    const int c0 = (tid & 15) * 8;
    float acc[4][8];
#pragma unroll
    for (int r = 0; r < 4; r++)
#pragma unroll
        for (int c = 0; c < 8; c++) acc[r][c] = 0.f;
#pragma unroll 4
    for (int k = 0; k < 64; k++) {
        float4 h  = *(const float4*)&sH[k*68 + r0];
        float4 w0 = *(const float4*)&sB[k*128 + c0];
        float4 w1 = *(const float4*)&sB[k*128 + c0 + 4];
        float hv[4] = {h.x, h.y, h.z, h.w};
        float wv[8] = {w0.x, w0.y, w0.z, w0.w, w1.x, w1.y, w1.z, w1.w};
#pragma unroll
        for (int r = 0; r < 4; r++)
#pragma unroll
            for (int c = 0; c < 8; c++)
                acc[r][c] = fmaf(hv[r], wv[c], acc[r][c]);
    }
#pragma unroll
    for (int r = 0; r < 4; r++) {
        *(float4*)&UV[(row0 + r0 + r)*128 + c0]     = make_float4(acc[r][0], acc[r][1], acc[r][2], acc[r][3]);
        *(float4*)&UV[(row0 + r0 + r)*128 + c0 + 4] = make_float4(acc[r][4], acc[r][5], acc[r][6], acc[r][7]);
    }
}

// ================= kernels =================

// L1: fps1 || knn1 || uv1  (all read only pos; fps blocks first)
__global__ void __launch_bounds__(256) l1_kernel(const float* __restrict__ pos,
                                                 int* __restrict__ sel1,
                                                 float* __restrict__ pos2,
                                                 int* __restrict__ idx1,
                                                 const float* __restrict__ W1a,
                                                 float* __restrict__ UV) {
    extern __shared__ float smd[];
    if (blockIdx.x < BB)
        fps_body<NP1, NP2>(pos, sel1, pos2, blockIdx.x, (float4*)smd);
    else if (blockIdx.x < BB + BB*NP1/256)
        knn_body<NP1, KK1>(pos, idx1, blockIdx.x - BB, (float4*)smd);
    else
        uv3_body(pos, W1a, UV, blockIdx.x - BB - BB*NP1/256, smd);
}

// L2: fps2 || knn2 || edge1  (fps2/knn2 need pos2 from L1; edge1 needs idx1/UV from L1)
__global__ void __launch_bounds__(256) l2_kernel(
    const float* __restrict__ pos2, int* __restrict__ sel2, float* __restrict__ pos3,
    int* __restrict__ idx2,
    const float* __restrict__ pos, const int* __restrict__ idx1,
    const float* __restrict__ UV, const float* __restrict__ Wrel,
    const float* __restrict__ ba, const float* __restrict__ Wb,
    const float* __restrict__ bb, float* __restrict__ h1)
{
    extern __shared__ float smd[];
    if (blockIdx.x < BB)
        fps_body<NP2, NP3>(pos2, sel2, pos3, blockIdx.x, (float4*)smd);
    else if (blockIdx.x < BB + BB*NP2/256)
        knn_body<NP2, KK2>(pos2, idx2, blockIdx.x - BB, (float4*)smd);
    else
        edge_body<NP1, KK1, 32>(pos, idx1, UV, Wrel, ba, Wb, bb, h1,
                                blockIdx.x - BB - BB*NP2/256, smd);
}

// L3: uv2-gather (needs h1)
__global__ void __launch_bounds__(256) uv2g_kernel(
    const float* __restrict__ h1, const int* __restrict__ sel1,
    const float* __restrict__ W2a, float* __restrict__ UV)
{
    extern __shared__ float smd[];
    uv64g_body<NP1, NP2>(h1, sel1, W2a, UV, blockIdx.x, smd);
}

// L4: edge2 || knn3
__global__ void __launch_bounds__(256) l4_kernel(
    const float* __restrict__ pos2, const int* __restrict__ idx2,
    const float* __restrict__ UV, const float* __restrict__ Wrel,
    const float* __restrict__ ba, const float* __restrict__ Wb,
    const float* __restrict__ bb, float* __restrict__ h2,
    const float* __restrict__ pos3, int* __restrict__ idx3)
{
    extern __shared__ float smd[];
    if (blockIdx.x < BB*NP2/32)
        edge_body<NP2, KK2, 32>(pos2, idx2, UV, Wrel, ba, Wb, bb, h2, blockIdx.x, smd);
    else
        knn_body<NP3, KK3>(pos3, idx3, blockIdx.x - BB*NP2/32, (float4*)smd);
}

// L5: uv3-gather
__global__ void __launch_bounds__(256) uv3g_kernel(
    const float* __restrict__ h2, const int* __restrict__ sel2,
    const float* __restrict__ W3a, float* __restrict__ UV)
{
    extern __shared__ float smd[];
    uv64g_body<NP2, NP3>(h2, sel2, W3a, UV, blockIdx.x, smd);
}

// L6: edge3
__global__ void __launch_bounds__(256) edge3_kernel(
    const float* __restrict__ pos3, const int* __restrict__ idx3,
    const float* __restrict__ UV, const float* __restrict__ Wrel,
    const float* __restrict__ ba, const float* __restrict__ Wb,
    const float* __restrict__ bb, float* __restrict__ h3)
{
    extern __shared__ float smd[];
    edge_body<NP3, KK3, 64>(pos3, idx3, UV, Wrel, ba, Wb, bb, h3, blockIdx.x, smd);
}

// head: global max-pool + [64x6] linear
__global__ void __launch_bounds__(64) head_kernel(const float* __restrict__ h3,
                                                  const float* __restrict__ Wr,
                                                  const float* __restrict__ br,
                                                  float* __restrict__ out) {
    __shared__ float g[64];
    const int b = blockIdx.x, c = threadIdx.x;
    float m = -3.4e38f;
#pragma unroll 2
    for (int p = 0; p < NP3; p++) m = fmaxf(m, h3[(b*NP3 + p)*64 + c]);
    g[c] = m;
    __syncthreads();
    if (c < 6) {
        float s = br[c];
#pragma unroll
        for (int dd = 0; dd < 64; dd++) s = fmaf(g[dd], Wr[dd*6 + c], s);
        out[b*6 + c] = s;
    }
}

extern "C" void kernel_launch(void* const* d_in, const int* in_sizes, int n_in,
                              void* d_out, int out_size) {
    const float* pos = (const float*)d_in[1];
    const float* W1a = (const float*)d_in[3];  const float* b1a = (const float*)d_in[4];
    const float* W1b = (const float*)d_in[5];  const float* b1b = (const float*)d_in[6];
    const float* W2a = (const float*)d_in[7];  const float* b2a = (const float*)d_in[8];
    const float* W2b = (const float*)d_in[9];  const float* b2b = (const float*)d_in[10];
    const float* W3a = (const float*)d_in[11]; const float* b3a = (const float*)d_in[12];
    const float* W3b = (const float*)d_in[13]; const float* b3b = (const float*)d_in[14];
    const float* Wr  = (const float*)d_in[15]; const float* br  = (const float*)d_in[16];
    float* out = (float*)d_out;

    const int smemL1 = NP1 * 16;                          // 32768 (fps1/knn1 pos)
    const int smemL2 = (64*(32*KK1 + 8) + 4096) * 4;      // 67584 (edge1; covers fps2/knn2 16KB)
    const int smemUV = (64*68 + 64*128) * 4;              // 50176
    const int smemL4 = (64*(32*KK2 + 8) + 4096) * 4;      // 51200 (edge2; covers knn3 8KB)
    const int smemL6 = (64*(64*4  + 8) + 4096) * 4;       // 83968
    cudaFuncSetAttribute(l1_kernel,    cudaFuncAttributeMaxDynamicSharedMemorySize, smemL1);
    cudaFuncSetAttribute(l2_kernel,    cudaFuncAttributeMaxDynamicSharedMemorySize, smemL2);
    cudaFuncSetAttribute(uv2g_kernel,  cudaFuncAttributeMaxDynamicSharedMemorySize, smemUV);
    cudaFuncSetAttribute(l4_kernel,    cudaFuncAttributeMaxDynamicSharedMemorySize, smemL4);
    cudaFuncSetAttribute(uv3g_kernel,  cudaFuncAttributeMaxDynamicSharedMemorySize, smemUV);
    cudaFuncSetAttribute(edge3_kernel, cudaFuncAttributeMaxDynamicSharedMemorySize, smemL6);

    float *uv, *h1, *pos2, *h2, *pos3, *h3;
    int *idx1, *sel1, *idx2, *sel2, *idx3;
    cudaGetSymbolAddress((void**)&uv,   g_uv);
    cudaGetSymbolAddress((void**)&h1,   g_h1);
    cudaGetSymbolAddress((void**)&idx1, g_idx1);
    cudaGetSymbolAddress((void**)&sel1, g_sel1);
    cudaGetSymbolAddress((void**)&pos2, g_pos2);
    cudaGetSymbolAddress((void**)&idx2, g_idx2);
    cudaGetSymbolAddress((void**)&h2,   g_h2);
    cudaGetSymbolAddress((void**)&sel2, g_sel2);
    cudaGetSymbolAddress((void**)&pos3, g_pos3);
    cudaGetSymbolAddress((void**)&idx3, g_idx3);
    cudaGetSymbolAddress((void**)&h3,   g_h3);

    // L1: fps1 || knn1 || uv1  (fps1 runs mostly alone after ~30us)
    l1_kernel<<<BB + BB*NP1/256 + BB*NP1/32, 256, smemL1>>>(
        pos, sel1, pos2, idx1, W1a, uv);
    // L2: fps2 || knn2 || edge1  (fps2 hides under edge1)
    l2_kernel<<<BB + BB*NP2/256 + BB*NP1/32, 256, smemL2>>>(
        pos2, sel2, pos3, idx2, pos, idx1, uv, W1a + 6*64, b1a, W1b, b1b, h1);
    // L3: uv2-gather
    uv2g_kernel<<<BB*NP2/64, 256, smemUV>>>(h1, sel1, W2a, uv);
    // L4: edge2 || knn3
    l4_kernel<<<BB*NP2/32 + BB*NP3/256, 256, smemL4>>>(
        pos2, idx2, uv, W2a + 128*64, b2a, W2b, b2b, h2, pos3, idx3);
    // L5: uv3-gather
    uv3g_kernel<<<BB*NP3/64, 256, smemUV>>>(h2, sel2, W3a, uv);
    // L6: edge3
    edge3_kernel<<<BB*NP3/64, 256, smemL6>>>(pos3, idx3, uv, W3a + 128*64, b3a, W3b, b3b, h3);
    // head
    head_kernel<<<BB, 64>>>(h3, Wr, br, out);
}